// round 10
// baseline (speedup 1.0000x reference)
#include <cuda_runtime.h>
#include <cstdint>

#define H 768
#define NB 64
#define S1 513
#define NROWS 32768

// out layout (flattened tuple, float32):
// isqa_pred(64), crf_pred(32768), isqa_loss(1), crf_loss(1), tags(32768), IsQA(64)
#define OFF_ISQA_PRED 0
#define OFF_CRF_PRED  64
#define OFF_ISQA_LOSS (64+32768)
#define OFF_CRF_LOSS  (64+32768+1)
#define OFF_TAGS      (64+32768+2)
#define OFF_ISQA      (64+32768+2+32768)

#define GRID 148
#define TPB 768
#define NWARP 24
#define SLOTS 3504      // 146 GEMV blocks * 24 warps
#define NTILES 8192     // 128 s-groups * 64 batches, 4 rows each

__device__ __align__(16) float g_feats[NROWS*4 + 4];    // [b][s][4]
__device__ __align__(16) float g_featsT[NROWS*4 + 64];  // [s][b][4]
// chunk-permuted exp(feats): s in 1..511 at [b*512 + ((s-1)&15)*32 + ((s-1)>>4)]
__device__ __align__(16) float g_efeatsP[NROWS*4];
__device__ float g_logits[2*NB];
__device__ float g_Z[NB];
__device__ float g_gold[NB];
__device__ unsigned g_cnt16[32];   // rows completed per 16-s chunk (target 1024)
__device__ unsigned g_scan_done;   // partition+gold warps done (target 128)
__device__ unsigned g_vit_done;    // block-0 viterbi warp done (target 1)

#define WAIT16(ix) do { volatile unsigned* _p = &g_cnt16[ix];                \
    while (*_p < 1024u) {} __threadfence(); } while (0)

// ---------------------------------------------------------------------------
// GEMV warp-tile: 4 rows (batch b, s0..s0+3), crfW in smem, publishes counter
// ---------------------------------------------------------------------------
__device__ __forceinline__ void gemv_tile(
    int tt, int lane,
    const float* __restrict__ emb, const float4* __restrict__ ws,
    const float* __restrict__ crfb)
{
    const int sgrp = tt >> 6;
    const int b = tt & 63;
    const int s0 = sgrp << 2;
    const int base0 = (b * S1 + s0 + 1) * H;
    float acc[4][4];
    #pragma unroll
    for (int r = 0; r < 4; r++)
        #pragma unroll
        for (int t = 0; t < 4; t++) acc[r][t] = 0.f;

    float4 ecur[4], enxt[4];
    #pragma unroll
    for (int r = 0; r < 4; r++)
        ecur[r] = __ldg((const float4*)&emb[base0 + r * H + lane * 4]);

    #pragma unroll
    for (int k = 0; k < 6; k++) {
        if (k < 5) {
            #pragma unroll
            for (int r = 0; r < 4; r++)
                enxt[r] = __ldg((const float4*)&emb[base0 + r * H + (k + 1) * 128 + lane * 4]);
        }
        float4 w[4];
        #pragma unroll
        for (int t = 0; t < 4; t++)
            w[t] = ws[t * 192 + k * 32 + lane];
        #pragma unroll
        for (int r = 0; r < 4; r++)
            #pragma unroll
            for (int t = 0; t < 4; t++)
                acc[r][t] += ecur[r].x * w[t].x + ecur[r].y * w[t].y
                           + ecur[r].z * w[t].z + ecur[r].w * w[t].w;
        #pragma unroll
        for (int r = 0; r < 4; r++) ecur[r] = enxt[r];
    }
    #pragma unroll
    for (int r = 0; r < 4; r++)
        #pragma unroll
        for (int t = 0; t < 4; t++) {
            float v = acc[r][t];
            v += __shfl_xor_sync(0xffffffffu, v, 16);
            v += __shfl_xor_sync(0xffffffffu, v, 8);
            v += __shfl_xor_sync(0xffffffffu, v, 4);
            v += __shfl_xor_sync(0xffffffffu, v, 2);
            v += __shfl_xor_sync(0xffffffffu, v, 1);
            acc[r][t] = v;
        }
    if (lane < 4) {
        const int s = s0 + lane;
        const int row = b * 512 + s;
        float4 o;
        o.x = acc[lane][0] + crfb[0];
        o.y = acc[lane][1] + crfb[1];
        o.z = acc[lane][2] + crfb[2];
        o.w = acc[lane][3] + crfb[3];
        *(float4*)&g_feats[row * 4] = o;
        *(float4*)&g_featsT[(s * 64 + b) * 4] = o;
        if (s > 0) {
            const int p = ((s - 1) & 15) * 32 + ((s - 1) >> 4);
            float4 eo;
            eo.x = __expf(o.x); eo.y = __expf(o.y);
            eo.z = __expf(o.z); eo.w = __expf(o.w);
            *(float4*)&g_efeatsP[(b * 512 + p) * 4] = eo;
        }
        __threadfence();
    }
    __syncwarp();
    if (lane == 0) atomicAdd(&g_cnt16[s0 >> 4], 4u);
}

// ---------------------------------------------------------------------------
// Viterbi: thread-per-batch lockstep warp; 4-step chunks, 2-deep prefetch,
// spin-tracks the GEMV producer via g_cnt16.
// ---------------------------------------------------------------------------
__device__ __forceinline__ void viterbi_warp(
    int lane, int b0v, const float* __restrict__ trans,
    float* __restrict__ out, uint32_t* sbp, unsigned char* spathB)
{
    const int b = b0v + lane;
    float T[16];
    #pragma unroll
    for (int i = 0; i < 16; i++) T[i] = trans[i];
    const float4* fT = (const float4*)g_featsT;

    #define VSTEP(f, byteref) {                                              \
        const float fa[4] = { (f).x, (f).y, (f).z, (f).w };                  \
        float nd[4];                                                         \
        unsigned bwork = 0;                                                  \
        _Pragma("unroll")                                                    \
        for (int j = 0; j < 4; j++) {                                        \
            const float s0 = d0 + T[j],     s1 = d1 + T[4 + j];              \
            const float s2 = d2 + T[8 + j], s3 = d3 + T[12 + j];             \
            const float m01 = fmaxf(s0, s1);                                 \
            const float m23 = fmaxf(s2, s3);                                 \
            nd[j] = fmaxf(m01, m23) + fa[j];                                 \
            const int bb = (m23 > m01) ? (2 + (int)(s3 > s2))                \
                                       : (int)(s1 > s0);                     \
            bwork |= (unsigned)bb << (2 * j);                                \
        }                                                                    \
        d0 = nd[0]; d1 = nd[1]; d2 = nd[2]; d3 = nd[3];                      \
        (byteref) = bwork; }

    // chunk c covers s = 4c+1 .. 4c+4 (c = 0..125 full; tail s=505..511)
    #define VCOMP4(buf, c) {                                                 \
        unsigned w = 0, byt;                                                 \
        _Pragma("unroll")                                                    \
        for (int u = 0; u < 4; u++) { VSTEP(buf[u], byt); w |= byt << (8*u); } \
        sbp[(c) * 32 + lane] = w; }

    #define VLOAD4(buf, c) {                                                 \
        _Pragma("unroll")                                                    \
        for (int u = 0; u < 4; u++) buf[u] = fT[((c)*4 + 1 + u)*64 + b]; }

    WAIT16(0);
    float4 f0 = fT[b];
    float d0 = f0.x + T[8], d1 = f0.y + T[9], d2 = f0.z + T[10], d3 = f0.w + T[11];
    float4 A[4], B[4];
    VLOAD4(A, 0);   // s 1..4   (chunk16 0)
    VLOAD4(B, 1);   // s 5..8   (chunk16 0)

    #pragma unroll 1
    for (int cc = 0; cc < 63; cc++) {
        VCOMP4(A, 2 * cc);
        const int pa = 2 * cc + 2;
        if (pa < 126) { WAIT16((4 * pa + 4) >> 4); VLOAD4(A, pa); }
        VCOMP4(B, 2 * cc + 1);
        const int pb = 2 * cc + 3;
        if (pb < 126) { WAIT16((4 * pb + 4) >> 4); VLOAD4(B, pb); }
    }
    // tail: s = 505..511 (chunk16 31)
    WAIT16(31);
    {
        float4 C[7];
        #pragma unroll
        for (int u = 0; u < 7; u++) C[u] = fT[(505 + u) * 64 + b];
        unsigned w0 = 0, w1 = 0, byt;
        #pragma unroll
        for (int u = 0; u < 4; u++) { VSTEP(C[u], byt); w0 |= byt << (8*u); }
        #pragma unroll
        for (int u = 4; u < 7; u++) { VSTEP(C[u], byt); w1 |= byt << (8*(u-4)); }
        sbp[126 * 32 + lane] = w0;
        sbp[127 * 32 + lane] = w1;
    }
    #undef VSTEP
    #undef VCOMP4
    #undef VLOAD4

    const float s0 = d0 + T[3], s1 = d1 + T[7], s2 = d2 + T[11], s3 = d3 + T[15];
    float mm = s0; int tag = 0;
    if (s1 > mm) { mm = s1; tag = 1; }
    if (s2 > mm) { mm = s2; tag = 2; }
    if (s3 > mm) { mm = s3; tag = 3; }
    spathB[511 * 33 + lane] = (unsigned char)tag;
    // backtrace: byte for step s=4c+1+u updates tag -> path[s-1]
    #pragma unroll 1
    for (int c = 127; c >= 0; c--) {
        const unsigned w = sbp[c * 32 + lane];
        #pragma unroll
        for (int u = 3; u >= 0; u--) {
            const int s = c * 4 + 1 + u;
            if (s > 511) continue;
            const unsigned byte = (w >> (8 * u)) & 0xffu;
            tag = (byte >> (2 * tag)) & 3;
            spathB[(s - 1) * 33 + lane] = (unsigned char)tag;
        }
    }
    __syncwarp();
    // coalesced dump
    for (int q = 0; q < 32; q++) {
        float* dst = out + OFF_CRF_PRED + (b0v + q) * 512;
        #pragma unroll
        for (int r = 0; r < 16; r++) {
            const int t = r * 32 + lane;
            dst[t] = (float)spathB[t * 33 + q];
        }
    }
}

// ---------------------------------------------------------------------------
// Fused persistent kernel
// ---------------------------------------------------------------------------
__global__ __launch_bounds__(TPB) void fused(
    const float* __restrict__ emb, const int* __restrict__ asl,
    const int* __restrict__ isqa,
    const float* __restrict__ fc2W, const float* __restrict__ fc2b,
    const float* __restrict__ crfW, const float* __restrict__ crfb,
    const float* __restrict__ trans, float* __restrict__ out)
{
    __shared__ float4 ws[768];                 // 12 KB (GEMV blocks)
    __shared__ uint32_t sbp[128 * 32];         // 16 KB (viterbi blocks)
    __shared__ unsigned char spathB[512 * 33]; // 16.9 KB (viterbi blocks)

    const int bx = blockIdx.x;
    const int tid = threadIdx.x;
    const int lane = tid & 31;
    const int winb = tid >> 5;

    if (bx == 0) {
        if (winb == 0) {
            viterbi_warp(lane, 0, trans, out, sbp, spathB);
            __threadfence();
            __syncwarp();
            if (lane == 0) atomicAdd(&g_vit_done, 1u);
        } else {
            // tags + IsQA passthrough (no dependencies)
            const int tc = tid - 32;  // 0..735
            for (int i = tc; i < NROWS; i += 736) {
                const int b = i >> 9, s = i & 511;
                out[OFF_TAGS + i] = (float)asl[b * S1 + 1 + s];
            }
            if (tc < NB) out[OFF_ISQA + tc] = (float)isqa[tc];
        }
        return;
    }

    if (bx == 9) {
        if (winb == 0) {
            viterbi_warp(lane, 32, trans, out, sbp, spathB);
        } else if (winb <= 8) {
            // cls logits: warp handles 8 batches
            float wa[6][4], wb[6][4];
            #pragma unroll
            for (int k = 0; k < 6; k++) {
                const int h = k * 128 + lane * 4;
                float4 va = *(const float4*)&fc2W[h];
                float4 vb = *(const float4*)&fc2W[H + h];
                wa[k][0] = va.x; wa[k][1] = va.y; wa[k][2] = va.z; wa[k][3] = va.w;
                wb[k][0] = vb.x; wb[k][1] = vb.y; wb[k][2] = vb.z; wb[k][3] = vb.w;
            }
            for (int q = 0; q < 8; q++) {
                const int b = (winb - 1) * 8 + q;
                const int base = b * S1 * H;
                float a0 = 0.f, a1 = 0.f;
                #pragma unroll
                for (int k = 0; k < 6; k++) {
                    float4 e = __ldg((const float4*)&emb[base + k * 128 + lane * 4]);
                    const float ec[4] = { e.x, e.y, e.z, e.w };
                    #pragma unroll
                    for (int c = 0; c < 4; c++) {
                        a0 += ec[c] * wa[k][c];
                        a1 += ec[c] * wb[k][c];
                    }
                }
                #pragma unroll
                for (int o = 16; o > 0; o >>= 1) {
                    a0 += __shfl_xor_sync(0xffffffffu, a0, o);
                    a1 += __shfl_xor_sync(0xffffffffu, a1, o);
                }
                if (lane == 0) {
                    g_logits[2 * b]     = a0 + fc2b[0];
                    g_logits[2 * b + 1] = a1 + fc2b[1];
                }
            }
        }
        __syncthreads();   // all 24 warps: viterbi+cls done, g_logits visible
        if (winb == 0) {
            // k3: single warp, 2 batches per lane
            if (lane == 0) {
                volatile unsigned* p1 = &g_scan_done;
                while (*p1 < 128u) {}
                volatile unsigned* p2 = &g_vit_done;
                while (*p2 < 1u) {}
            }
            __syncwarp();
            __threadfence();
            float diff = 0.f, lossb = 0.f;
            #pragma unroll
            for (int q = 0; q < 2; q++) {
                const int t = lane + 32 * q;
                diff += g_Z[t] - g_gold[t];
                const float l0 = g_logits[2 * t], l1 = g_logits[2 * t + 1];
                const float m = fmaxf(l0, l1);
                const float lse = m + __logf(__expf(l0 - m) + __expf(l1 - m));
                const int qq = isqa[t];
                lossb += lse - (qq ? l1 : l0);
                out[OFF_ISQA_PRED + t] = (l1 > l0) ? 1.0f : 0.0f;
            }
            #pragma unroll
            for (int o = 16; o > 0; o >>= 1) {
                diff  += __shfl_xor_sync(0xffffffffu, diff, o);
                lossb += __shfl_xor_sync(0xffffffffu, lossb, o);
            }
            if (lane == 0) {
                out[OFF_CRF_LOSS]  = diff  * (1.0f / 64.0f);
                out[OFF_ISQA_LOSS] = lossb * (1.0f / 64.0f);
                // reset counters for next graph replay (all consumers done)
                #pragma unroll
                for (int i = 0; i < 32; i++) g_cnt16[i] = 0u;
                g_scan_done = 0u;
                g_vit_done = 0u;
            }
        }
        return;
    }

    // ================= GEMV blocks (1..8, 10..147) =================
    ws[tid < 768 ? tid : 0] = ((const float4*)crfW)[tid < 768 ? tid : 0];
    __syncthreads();
    const int slot = (bx <= 8 ? (bx - 1) : (bx - 2)) * NWARP + winb;
    #pragma unroll 1
    for (int it = 0; it < 3; it++) {
        const int tt = slot + it * SLOTS;
        if (tt < NTILES) gemv_tile(tt, lane, emb, ws, crfb);
    }
    if (bx > 8) return;

    // wait for ALL feats: each lane spins on its chunk counter
    {
        volatile unsigned* p = &g_cnt16[lane];
        while (*p < 1024u) {}
    }
    __syncwarp();
    __threadfence();

    if (bx <= 4) {
        // ============ PARTITION (warp per batch) ============
        const int b = (bx - 1) * NWARP + winb;
        if (b >= NB) return;
        float E[4][4];
        #pragma unroll
        for (int i = 0; i < 4; i++)
            #pragma unroll
            for (int j = 0; j < 4; j++) E[i][j] = expf(trans[i * 4 + j]);

        const float4* eb = (const float4*)g_efeatsP + b * 512;
        float m[16];
        float lg = 0.f;

        #define RENORM() {                                                   \
            float mx = m[0];                                                 \
            _Pragma("unroll")                                                \
            for (int q = 1; q < 16; q++) mx = fmaxf(mx, m[q]);               \
            const float inv = __fdividef(1.f, mx);                           \
            _Pragma("unroll")                                                \
            for (int q = 0; q < 16; q++) m[q] *= inv;                        \
            lg += __logf(mx); }

        #define MSTEP(e4) {                                                  \
            const float ee[4] = { (e4).x, (e4).y, (e4).z, (e4).w };          \
            float nm[16];                                                    \
            _Pragma("unroll")                                                \
            for (int i = 0; i < 4; i++)                                      \
                _Pragma("unroll")                                            \
                for (int j = 0; j < 4; j++)                                  \
                    nm[i*4+j] = ((m[i*4+0]*E[0][j] + m[i*4+1]*E[1][j])       \
                               + (m[i*4+2]*E[2][j] + m[i*4+3]*E[3][j])) * ee[j]; \
            _Pragma("unroll")                                                \
            for (int q = 0; q < 16; q++) m[q] = nm[q]; }

        #pragma unroll 1
        for (int g = 0; g < 4; g++) {
            float4 ld[4];
            #pragma unroll
            for (int u = 0; u < 4; u++) ld[u] = eb[(g * 4 + u) * 32 + lane];
            if (g == 0) {
                #pragma unroll
                for (int i = 0; i < 4; i++) {
                    m[i*4+0] = E[i][0] * ld[0].x;
                    m[i*4+1] = E[i][1] * ld[0].y;
                    m[i*4+2] = E[i][2] * ld[0].z;
                    m[i*4+3] = E[i][3] * ld[0].w;
                }
                #pragma unroll
                for (int u = 1; u < 4; u++) MSTEP(ld[u]);
            } else {
                #pragma unroll
                for (int u = 0; u < 4; u++) {
                    if (g < 3 || u < 3 || lane < 31) MSTEP(ld[u]);
                }
            }
            if (g == 1 || g == 3) RENORM();
        }
        #pragma unroll
        for (int off = 1; off < 32; off <<= 1) {
            float pm[16], plg;
            #pragma unroll
            for (int q = 0; q < 16; q++)
                pm[q] = __shfl_up_sync(0xffffffffu, m[q], off);
            plg = __shfl_up_sync(0xffffffffu, lg, off);
            if (lane >= off) {
                float nm[16];
                #pragma unroll
                for (int i = 0; i < 4; i++)
                    #pragma unroll
                    for (int j = 0; j < 4; j++)
                        nm[i*4+j] = ((pm[i*4+0]*m[0*4+j] + pm[i*4+1]*m[1*4+j])
                                   + (pm[i*4+2]*m[2*4+j] + pm[i*4+3]*m[3*4+j]));
                #pragma unroll
                for (int q = 0; q < 16; q++) m[q] = nm[q];
                lg += plg;
                RENORM();
            }
        }
        if (lane == 31) {
            float4 f0 = *(const float4*)&g_feats[b * 2048];
            const float x0 = f0.x + trans[8],  x1 = f0.y + trans[9];
            const float x2 = f0.z + trans[10], x3 = f0.w + trans[11];
            const float m0 = fmaxf(fmaxf(x0, x1), fmaxf(x2, x3));
            const float a0 = __expf(x0 - m0), a1 = __expf(x1 - m0);
            const float a2 = __expf(x2 - m0), a3 = __expf(x3 - m0);
            float z = 0.f;
            #pragma unroll
            for (int j = 0; j < 4; j++) {
                const float vj = a0 * m[0*4+j] + a1 * m[1*4+j]
                               + a2 * m[2*4+j] + a3 * m[3*4+j];
                z += vj * E[j][3];
            }
            g_Z[b] = m0 + lg + __logf(z);
            __threadfence();
            atomicAdd(&g_scan_done, 1u);
        }
        #undef MSTEP
        #undef RENORM
    } else {
        // ============ GOLD (warp per batch) ============
        const int b = (bx - 5) * NWARP + winb;
        if (b >= NB) return;
        const int abase = b * S1 + 1 + lane * 16;
        int tg[16];
        #pragma unroll
        for (int u = 0; u < 16; u++) tg[u] = asl[abase + u];
        float s = 0.f;
        #pragma unroll
        for (int u = 0; u < 16; u++)
            s += g_feats[((b << 9) + lane * 16 + u) * 4 + tg[u]];
        const int tnext0 = __shfl_down_sync(0xffffffffu, tg[0], 1);
        #pragma unroll
        for (int u = 0; u < 15; u++)
            s += __ldg(&trans[tg[u] * 4 + tg[u + 1]]);
        if (lane < 31) s += __ldg(&trans[tg[15] * 4 + tnext0]);
        if (lane == 0)  s += __ldg(&trans[8 + tg[0]]);
        if (lane == 31) s += __ldg(&trans[tg[15] * 4 + 3]);
        #pragma unroll
        for (int o = 16; o > 0; o >>= 1) s += __shfl_xor_sync(0xffffffffu, s, o);
        if (lane == 0) {
            g_gold[b] = s;
            __threadfence();
            atomicAdd(&g_scan_done, 1u);
        }
    }
}

extern "C" void kernel_launch(void* const* d_in, const int* in_sizes, int n_in,
                              void* d_out, int out_size)
{
    const float* emb  = (const float*)d_in[0];
    const int*   asl  = (const int*)d_in[1];
    const int*   isqa = (const int*)d_in[2];
    const float* fc2W = (const float*)d_in[3];
    const float* fc2b = (const float*)d_in[4];
    const float* crfW = (const float*)d_in[5];
    const float* crfb = (const float*)d_in[6];
    const float* trans= (const float*)d_in[7];
    float* out = (float*)d_out;

    fused<<<GRID, TPB>>>(emb, asl, isqa, fc2W, fc2b, crfW, crfb, trans, out);
}

// round 16
// speedup vs baseline: 2.2540x; 2.2540x over previous
#include <cuda_runtime.h>
#include <cstdint>

#define H 768
#define NB 64
#define S1 513
#define NROWS 32768

// out layout (flattened tuple, float32):
// isqa_pred(64), crf_pred(32768), isqa_loss(1), crf_loss(1), tags(32768), IsQA(64)
#define OFF_ISQA_PRED 0
#define OFF_CRF_PRED  64
#define OFF_ISQA_LOSS (64+32768)
#define OFF_CRF_LOSS  (64+32768+1)
#define OFF_TAGS      (64+32768+2)
#define OFF_ISQA      (64+32768+2+32768)

__device__ __align__(16) float g_feats[NROWS*4 + 4];    // [b][s][4]
__device__ __align__(16) float g_featsT[NROWS*4 + 64];  // [s][b][4]
// chunk-permuted exp(feats): s in 1..511 at [b*512 + ((s-1)&15)*32 + ((s-1)>>4)]
__device__ __align__(16) float g_efeatsP[NROWS*4];
__device__ float g_logits[2*NB];
__device__ float g_Z[NB];
__device__ float g_gold[NB];
__device__ unsigned g_scan_done;   // partition(64) + gold(64) warps, target 128

// ---------------------------------------------------------------------------
// K1: feats GEMV (blocks 0..2047: warp = 2 rows, 12 front-batched LDG.128,
//     crfW in smem), cls GEMV (2048..2055), tag/IsQA copy (2056..2063)
// ---------------------------------------------------------------------------
__global__ __launch_bounds__(256, 3) void k1(
    const float* __restrict__ emb, const int* __restrict__ asl,
    const int* __restrict__ isqa,
    const float* __restrict__ fc2W, const float* __restrict__ fc2b,
    const float* __restrict__ crfW, const float* __restrict__ crfb,
    float* __restrict__ out)
{
    const int bx = blockIdx.x;
    const int lane = threadIdx.x & 31;
    const int winb = threadIdx.x >> 5;

    if (bx < 2048) {
        __shared__ float4 ws[768];  // ws[t*192 + j] = crfW[t][4j..4j+3]
        for (int i = threadIdx.x; i < 768; i += 256)
            ws[i] = ((const float4*)crfW)[i];
        __syncthreads();

        const int row0 = (bx * 8 + winb) * 2;
        const int b0 = row0 >> 9, s0v = row0 & 511;   // 2 rows share batch b0
        const int base0 = (b0 * S1 + s0v + 1) * H;

        // front-batch all 12 loads (MLP=12)
        float4 ea[6], eb4[6];
        #pragma unroll
        for (int k = 0; k < 6; k++)
            ea[k] = __ldg((const float4*)&emb[base0 + k * 128 + lane * 4]);
        #pragma unroll
        for (int k = 0; k < 6; k++)
            eb4[k] = __ldg((const float4*)&emb[base0 + H + k * 128 + lane * 4]);

        float acc0[4] = {0.f, 0.f, 0.f, 0.f};
        float acc1[4] = {0.f, 0.f, 0.f, 0.f};
        #pragma unroll
        for (int k = 0; k < 6; k++) {
            float4 w[4];
            #pragma unroll
            for (int t = 0; t < 4; t++)
                w[t] = ws[t * 192 + k * 32 + lane];
            #pragma unroll
            for (int t = 0; t < 4; t++) {
                acc0[t] += ea[k].x * w[t].x + ea[k].y * w[t].y
                         + ea[k].z * w[t].z + ea[k].w * w[t].w;
                acc1[t] += eb4[k].x * w[t].x + eb4[k].y * w[t].y
                         + eb4[k].z * w[t].z + eb4[k].w * w[t].w;
            }
        }
        #pragma unroll
        for (int t = 0; t < 4; t++) {
            float v0 = acc0[t], v1 = acc1[t];
            #pragma unroll
            for (int o = 16; o > 0; o >>= 1) {
                v0 += __shfl_xor_sync(0xffffffffu, v0, o);
                v1 += __shfl_xor_sync(0xffffffffu, v1, o);
            }
            acc0[t] = v0; acc1[t] = v1;
        }
        if (lane < 2) {
            const int s = s0v + lane;
            const int row = row0 + lane;
            float4 o;
            o.x = (lane == 0 ? acc0[0] : acc1[0]) + crfb[0];
            o.y = (lane == 0 ? acc0[1] : acc1[1]) + crfb[1];
            o.z = (lane == 0 ? acc0[2] : acc1[2]) + crfb[2];
            o.w = (lane == 0 ? acc0[3] : acc1[3]) + crfb[3];
            *(float4*)&g_feats[row * 4] = o;
            *(float4*)&g_featsT[(s * 64 + b0) * 4] = o;
            if (s > 0) {
                const int p = ((s - 1) & 15) * 32 + ((s - 1) >> 4);
                float4 eo;
                eo.x = __expf(o.x); eo.y = __expf(o.y);
                eo.z = __expf(o.z); eo.w = __expf(o.w);
                *(float4*)&g_efeatsP[(b0 * 512 + p) * 4] = eo;
            }
        }
    } else if (bx < 2056) {
        // cls logits: warp per batch element
        const int b = (bx - 2048) * 8 + winb;
        float wa[6][4], wb[6][4];
        #pragma unroll
        for (int k = 0; k < 6; k++) {
            const int h = k * 128 + lane * 4;
            float4 va = *(const float4*)&fc2W[h];
            float4 vb = *(const float4*)&fc2W[H + h];
            wa[k][0] = va.x; wa[k][1] = va.y; wa[k][2] = va.z; wa[k][3] = va.w;
            wb[k][0] = vb.x; wb[k][1] = vb.y; wb[k][2] = vb.z; wb[k][3] = vb.w;
        }
        const int base = b * S1 * H;  // emb[:,0]
        float a0 = 0.f, a1 = 0.f;
        #pragma unroll
        for (int k = 0; k < 6; k++) {
            float4 e = __ldg((const float4*)&emb[base + k * 128 + lane * 4]);
            const float ec[4] = { e.x, e.y, e.z, e.w };
            #pragma unroll
            for (int c = 0; c < 4; c++) {
                a0 += ec[c] * wa[k][c];
                a1 += ec[c] * wb[k][c];
            }
        }
        #pragma unroll
        for (int o = 16; o > 0; o >>= 1) {
            a0 += __shfl_xor_sync(0xffffffffu, a0, o);
            a1 += __shfl_xor_sync(0xffffffffu, a1, o);
        }
        if (lane == 0) {
            g_logits[2 * b]     = a0 + fc2b[0];
            g_logits[2 * b + 1] = a1 + fc2b[1];
        }
    } else {
        // copies: tags + IsQA passthrough
        const int tid = (bx - 2056) * 256 + threadIdx.x;
        for (int i = tid; i < NROWS; i += 2048) {
            const int b = i >> 9, s = i & 511;
            out[OFF_TAGS + i] = (float)asl[b * S1 + 1 + s];
        }
        if (tid < NB) out[OFF_ISQA + tid] = (float)isqa[tid];
    }
}

// ---------------------------------------------------------------------------
// K2: bx 0,1   = viterbi, thread-per-batch, 2-chunk-deep pipelined loads
//     bx 2..9  = log-partition (warp per batch, chunked semiring scan)
//     bx 10..17= gold score (warp per batch, batched two-wave loads)
//     bx 18    = losses + isqa preds (spins on g_scan_done)
// ---------------------------------------------------------------------------
__global__ __launch_bounds__(256) void k2(
    const int* __restrict__ asl, const int* __restrict__ isqa,
    const float* __restrict__ trans, float* __restrict__ out)
{
    __shared__ uint32_t sbp[128 * 32];         // [2*chunk + w][lane]
    __shared__ unsigned char spathB[512 * 33]; // [t][lane] padded stride 33
    __shared__ float strans[16];

    const int bx = blockIdx.x;
    const int lane = threadIdx.x & 31;
    const int winb = threadIdx.x >> 5;

    if (bx < 2) {
        // ================= VITERBI (thread-per-batch) =================
        if (winb != 0) return;
        const int b = bx * 32 + lane;
        float T[16];
        #pragma unroll
        for (int i = 0; i < 16; i++) T[i] = trans[i];

        const float4* fT = (const float4*)g_featsT;
        float4 f0 = fT[b];  // s=0 row
        float d0 = f0.x + T[8], d1 = f0.y + T[9], d2 = f0.z + T[10], d3 = f0.w + T[11];

        #define VSTEP(f, byteref) {                                          \
            const float fa[4] = { (f).x, (f).y, (f).z, (f).w };              \
            float nd[4];                                                     \
            unsigned bwork = 0;                                              \
            _Pragma("unroll")                                                \
            for (int j = 0; j < 4; j++) {                                    \
                const float s0 = d0 + T[j],     s1 = d1 + T[4 + j];          \
                const float s2 = d2 + T[8 + j], s3 = d3 + T[12 + j];         \
                const float m01 = fmaxf(s0, s1);                             \
                const float m23 = fmaxf(s2, s3);                             \
                nd[j] = fmaxf(m01, m23) + fa[j];                             \
                const int bb = (m23 > m01) ? (2 + (int)(s3 > s2))            \
                                           : (int)(s1 > s0);                 \
                bwork |= (unsigned)bb << (2 * j);                            \
            }                                                                \
            d0 = nd[0]; d1 = nd[1]; d2 = nd[2]; d3 = nd[3];                  \
            (byteref) = bwork; }

        #define VCOMPUTE(buf, c) {                                           \
            unsigned w0 = 0, w1 = 0, byt;                                    \
            _Pragma("unroll")                                                \
            for (int u = 0; u < 4; u++) { VSTEP(buf[u], byt); w0 |= byt << (8*u); } \
            _Pragma("unroll")                                                \
            for (int u = 4; u < 8; u++) { VSTEP(buf[u], byt); w1 |= byt << (8*(u-4)); } \
            sbp[(2*(c))*32 + lane] = w0;                                     \
            sbp[(2*(c)+1)*32 + lane] = w1; }

        #define VLOAD(buf, c) {                                              \
            const int vc = ((c) < 62 ? (c) : 62);                            \
            _Pragma("unroll")                                                \
            for (int u = 0; u < 8; u++) buf[u] = fT[(vc*8 + 1 + u)*64 + b]; }

        // full chunks c=0..62 cover s=1..504; tail C covers s=505..511
        float4 A[8], B[8], C[7];
        #pragma unroll
        for (int u = 0; u < 8; u++) A[u] = fT[(1 + u) * 64 + b];
        #pragma unroll
        for (int u = 0; u < 8; u++) B[u] = fT[(9 + u) * 64 + b];
        #pragma unroll
        for (int u = 0; u < 7; u++) C[u] = fT[(505 + u) * 64 + b];

        #pragma unroll 1
        for (int cc = 0; cc < 31; cc++) {
            VCOMPUTE(A, 2 * cc);     VLOAD(A, 2 * cc + 2);
            VCOMPUTE(B, 2 * cc + 1); VLOAD(B, 2 * cc + 3);
        }
        VCOMPUTE(A, 62);
        {   // tail chunk c=63: 7 steps
            unsigned w0 = 0, w1 = 0, byt;
            #pragma unroll
            for (int u = 0; u < 4; u++) { VSTEP(C[u], byt); w0 |= byt << (8*u); }
            #pragma unroll
            for (int u = 4; u < 7; u++) { VSTEP(C[u], byt); w1 |= byt << (8*(u-4)); }
            sbp[126 * 32 + lane] = w0;
            sbp[127 * 32 + lane] = w1;
        }
        #undef VSTEP
        #undef VCOMPUTE
        #undef VLOAD

        const float s0 = d0 + T[3], s1 = d1 + T[7], s2 = d2 + T[11], s3 = d3 + T[15];
        float mm = s0; int tag = 0;
        if (s1 > mm) { mm = s1; tag = 1; }
        if (s2 > mm) { mm = s2; tag = 2; }
        if (s3 > mm) { mm = s3; tag = 3; }
        spathB[511 * 33 + lane] = (unsigned char)tag;
        // backtrace: byte for step s=8c+1+u updates tag -> path[s-1]
        #pragma unroll 1
        for (int c = 63; c >= 0; c--) {
            const unsigned w0 = sbp[(2*c)*32 + lane];
            const unsigned w1 = sbp[(2*c+1)*32 + lane];
            #pragma unroll
            for (int u = 7; u >= 4; u--) {
                const int s = c * 8 + 1 + u;
                if (s > 511) continue;
                const unsigned byte = (w1 >> (8 * (u - 4))) & 0xffu;
                tag = (byte >> (2 * tag)) & 3;
                spathB[(s - 1) * 33 + lane] = (unsigned char)tag;
            }
            #pragma unroll
            for (int u = 3; u >= 0; u--) {
                const int s = c * 8 + 1 + u;
                const unsigned byte = (w0 >> (8 * u)) & 0xffu;
                tag = (byte >> (2 * tag)) & 3;
                spathB[(s - 1) * 33 + lane] = (unsigned char)tag;
            }
        }
        __syncwarp();
        // coalesced dump: for each batch column, lanes sweep t
        for (int q = 0; q < 32; q++) {
            float* dst = out + OFF_CRF_PRED + (bx * 32 + q) * 512;
            #pragma unroll
            for (int r = 0; r < 16; r++) {
                const int t = r * 32 + lane;
                dst[t] = (float)spathB[t * 33 + q];
            }
        }
    } else if (bx < 10) {
        // ================= PARTITION (chunked linear-domain scan) ==========
        const int b = (bx - 2) * 8 + winb;
        float E[4][4];
        #pragma unroll
        for (int i = 0; i < 4; i++)
            #pragma unroll
            for (int j = 0; j < 4; j++) E[i][j] = expf(trans[i * 4 + j]);

        const float4* eb = (const float4*)g_efeatsP + b * 512;
        float m[16];
        float lg = 0.f;

        #define RENORM() {                                                   \
            float mx = m[0];                                                 \
            _Pragma("unroll")                                                \
            for (int q = 1; q < 16; q++) mx = fmaxf(mx, m[q]);               \
            const float inv = __fdividef(1.f, mx);                           \
            _Pragma("unroll")                                                \
            for (int q = 0; q < 16; q++) m[q] *= inv;                        \
            lg += __logf(mx); }

        #define MSTEP(e4) {                                                  \
            const float ee[4] = { (e4).x, (e4).y, (e4).z, (e4).w };          \
            float nm[16];                                                    \
            _Pragma("unroll")                                                \
            for (int i = 0; i < 4; i++)                                      \
                _Pragma("unroll")                                            \
                for (int j = 0; j < 4; j++)                                  \
                    nm[i*4+j] = ((m[i*4+0]*E[0][j] + m[i*4+1]*E[1][j])       \
                               + (m[i*4+2]*E[2][j] + m[i*4+3]*E[3][j])) * ee[j]; \
            _Pragma("unroll")                                                \
            for (int q = 0; q < 16; q++) m[q] = nm[q]; }

        {
            float4 ld[8];
            #pragma unroll
            for (int u = 0; u < 8; u++) ld[u] = eb[u * 32 + lane];
            #pragma unroll
            for (int i = 0; i < 4; i++) {
                m[i*4+0] = E[i][0] * ld[0].x;
                m[i*4+1] = E[i][1] * ld[0].y;
                m[i*4+2] = E[i][2] * ld[0].z;
                m[i*4+3] = E[i][3] * ld[0].w;
            }
            #pragma unroll
            for (int u = 1; u < 8; u++) MSTEP(ld[u]);
            RENORM();
            #pragma unroll
            for (int u = 0; u < 8; u++) ld[u] = eb[(u + 8) * 32 + lane];
            #pragma unroll
            for (int u = 8; u < 16; u++) {
                if (lane < 31 || u < 15) MSTEP(ld[u - 8]);
            }
            RENORM();
        }
        #pragma unroll
        for (int off = 1; off < 32; off <<= 1) {
            float pm[16], plg;
            #pragma unroll
            for (int q = 0; q < 16; q++)
                pm[q] = __shfl_up_sync(0xffffffffu, m[q], off);
            plg = __shfl_up_sync(0xffffffffu, lg, off);
            if (lane >= off) {
                float nm[16];
                #pragma unroll
                for (int i = 0; i < 4; i++)
                    #pragma unroll
                    for (int j = 0; j < 4; j++)
                        nm[i*4+j] = ((pm[i*4+0]*m[0*4+j] + pm[i*4+1]*m[1*4+j])
                                   + (pm[i*4+2]*m[2*4+j] + pm[i*4+3]*m[3*4+j]));
                #pragma unroll
                for (int q = 0; q < 16; q++) m[q] = nm[q];
                lg += plg;
                RENORM();
            }
        }
        if (lane == 31) {
            float4 f0 = *(const float4*)&g_feats[b * 2048];
            const float x0 = f0.x + trans[8],  x1 = f0.y + trans[9];
            const float x2 = f0.z + trans[10], x3 = f0.w + trans[11];
            const float m0 = fmaxf(fmaxf(x0, x1), fmaxf(x2, x3));
            const float a0 = __expf(x0 - m0), a1 = __expf(x1 - m0);
            const float a2 = __expf(x2 - m0), a3 = __expf(x3 - m0);
            float z = 0.f;
            #pragma unroll
            for (int j = 0; j < 4; j++) {
                const float vj = a0 * m[0*4+j] + a1 * m[1*4+j]
                               + a2 * m[2*4+j] + a3 * m[3*4+j];
                z += vj * E[j][3];
            }
            g_Z[b] = m0 + lg + __logf(z);
            __threadfence();
            atomicAdd(&g_scan_done, 1u);
        }
        #undef MSTEP
        #undef RENORM
    } else if (bx < 18) {
        // ================= GOLD (warp per batch, two-wave batched loads) ===
        if (threadIdx.x < 16) strans[threadIdx.x] = trans[threadIdx.x];
        __syncthreads();
        const int b = (bx - 10) * 8 + winb;
        const int abase = b * S1 + 1 + lane * 16;
        int tg[16];
        #pragma unroll
        for (int u = 0; u < 16; u++) tg[u] = asl[abase + u];
        float s = 0.f;
        #pragma unroll
        for (int u = 0; u < 16; u++)
            s += g_feats[((b << 9) + lane * 16 + u) * 4 + tg[u]];
        const int tnext0 = __shfl_down_sync(0xffffffffu, tg[0], 1);
        #pragma unroll
        for (int u = 0; u < 15; u++)
            s += strans[tg[u] * 4 + tg[u + 1]];
        if (lane < 31) s += strans[tg[15] * 4 + tnext0];
        if (lane == 0)  s += strans[8 + tg[0]];
        if (lane == 31) s += strans[tg[15] * 4 + 3];
        #pragma unroll
        for (int o = 16; o > 0; o >>= 1) s += __shfl_xor_sync(0xffffffffu, s, o);
        if (lane == 0) {
            g_gold[b] = s;
            __threadfence();
            atomicAdd(&g_scan_done, 1u);
        }
    } else {
        // ================= LOSSES + ISQA PRED (single warp, spins) =========
        if (winb != 0) return;
        if (lane == 0) {
            volatile unsigned* p = &g_scan_done;
            while (*p < 128u) __nanosleep(200);
        }
        __syncwarp();
        __threadfence();
        float diff = 0.f, lossb = 0.f;
        #pragma unroll
        for (int q = 0; q < 2; q++) {
            const int t = lane + 32 * q;
            diff += g_Z[t] - g_gold[t];
            const float l0 = g_logits[2 * t], l1 = g_logits[2 * t + 1];
            const float m = fmaxf(l0, l1);
            const float lse = m + __logf(__expf(l0 - m) + __expf(l1 - m));
            const int qq = isqa[t];
            lossb += lse - (qq ? l1 : l0);
            out[OFF_ISQA_PRED + t] = (l1 > l0) ? 1.0f : 0.0f;
        }
        #pragma unroll
        for (int o = 16; o > 0; o >>= 1) {
            diff  += __shfl_xor_sync(0xffffffffu, diff, o);
            lossb += __shfl_xor_sync(0xffffffffu, lossb, o);
        }
        if (lane == 0) {
            out[OFF_CRF_LOSS]  = diff  * (1.0f / 64.0f);
            out[OFF_ISQA_LOSS] = lossb * (1.0f / 64.0f);
            g_scan_done = 0u;   // reset for next graph replay (sole consumer)
        }
    }
}

extern "C" void kernel_launch(void* const* d_in, const int* in_sizes, int n_in,
                              void* d_out, int out_size)
{
    const float* emb  = (const float*)d_in[0];
    const int*   asl  = (const int*)d_in[1];
    const int*   isqa = (const int*)d_in[2];
    const float* fc2W = (const float*)d_in[3];
    const float* fc2b = (const float*)d_in[4];
    const float* crfW = (const float*)d_in[5];
    const float* crfb = (const float*)d_in[6];
    const float* trans= (const float*)d_in[7];
    float* out = (float*)d_out;

    k1<<<2064, 256>>>(emb, asl, isqa, fc2W, fc2b, crfW, crfb, out);
    k2<<<19, 256>>>(asl, isqa, trans, out);
}